// round 1
// baseline (speedup 1.0000x reference)
#include <cuda_runtime.h>
#include <cuda_bf16.h>
#include <math.h>

// ---------------------------------------------------------------------------
// Problem constants
// ---------------------------------------------------------------------------
#define BATCH 8
#define SV    257
#define SQ    2048
#define DV    1024
#define DM    2304
#define NH    8
#define DK    288          // DM / NH
#define DF    9216         // 4 * DM
#define ROWS_T (BATCH*SQ)  // 16384
#define ROWS_V (BATCH*SV)  // 2056

// ---------------------------------------------------------------------------
// Scratch (device globals; no runtime allocation allowed)
// ---------------------------------------------------------------------------
__device__ float g_pv [(size_t)ROWS_V * DM];   // vision projection
__device__ float g_nt [(size_t)ROWS_T * DM];   // ln1(text) / ln2(x) (reused)
__device__ float g_q  [(size_t)ROWS_T * DM];
__device__ float g_k  [(size_t)ROWS_V * DM];
__device__ float g_v  [(size_t)ROWS_V * DM];
__device__ float g_ctx[(size_t)ROWS_T * DM];
__device__ float g_x  [(size_t)ROWS_T * DM];   // text + att_out
__device__ float g_h  [(size_t)ROWS_T * DF];   // FFN hidden

// ---------------------------------------------------------------------------
// f32x2 packed-math helpers (sm_103a FFMA2 path — PTX only, per SASS quickref)
// ---------------------------------------------------------------------------
__device__ __forceinline__ unsigned long long pk2(float a) {
    unsigned long long r;
    unsigned int u = __float_as_uint(a);
    asm("mov.b64 %0, {%1, %1};" : "=l"(r) : "r"(u));
    return r;
}
__device__ __forceinline__ void fma2(unsigned long long& d,
                                     unsigned long long a,
                                     unsigned long long b) {
    asm("fma.rn.f32x2 %0, %1, %2, %0;" : "+l"(d) : "l"(a), "l"(b));
}
__device__ __forceinline__ float2 unpk2(unsigned long long v) {
    float2 f;
    asm("mov.b64 {%0, %1}, %2;" : "=f"(f.x), "=f"(f.y) : "l"(v));
    return f;
}
__device__ __forceinline__ float gelu_exact(float x) {
    return 0.5f * x * (1.0f + erff(x * 0.70710678118654752f));
}

// ---------------------------------------------------------------------------
// Tiled SGEMM: C[M,N] = A[M,K] @ B[K,N] + bias (+ epilogue)
//   EPI 0: + bias
//   EPI 1: + bias + res[row,col]
//   EPI 2: gelu(+ bias)
// BM=BN=128, BK=16, 256 threads, 8x8 outputs/thread as 32 f32x2 accumulators.
// Requirements: K % 16 == 0, N % 128 == 0 (true for all call sites). M guarded.
// ---------------------------------------------------------------------------
#define BM 128
#define BN 128
#define BK 16

template <int EPI>
__global__ void __launch_bounds__(256, 2)
sgemm_kernel(const float* __restrict__ A, const float* __restrict__ B,
             const float* __restrict__ bias, const float* __restrict__ res,
             float* __restrict__ C, int M, int N, int K)
{
    __shared__ float As[BK][BM];   // transposed A tile
    __shared__ float Bs[BK][BN];

    const int bm = blockIdx.y * BM;
    const int bn = blockIdx.x * BN;
    const int tid = threadIdx.x;
    const int tx = tid & 15;    // N direction (8 cols each)
    const int ty = tid >> 4;    // M direction (8 rows each)

    unsigned long long acc[8][4];
#pragma unroll
    for (int m = 0; m < 8; m++)
#pragma unroll
        for (int n = 0; n < 4; n++) acc[m][n] = 0ull;

    // A-tile load mapping: 128 rows x 4 float4; thread handles l=tid, tid+256
    const int ar0 = tid >> 2;          // 0..63
    const int ac0 = (tid & 3) * 4;     // 0,4,8,12
    // B-tile load mapping: 16 rows x 32 float4
    const int br0 = tid >> 5;          // 0..7
    const int bc0 = (tid & 31) * 4;    // 0..124

    for (int k0 = 0; k0 < K; k0 += BK) {
        float4 av0 = make_float4(0.f, 0.f, 0.f, 0.f);
        float4 av1 = av0;
        if (bm + ar0 < M)
            av0 = *(const float4*)&A[(size_t)(bm + ar0) * K + k0 + ac0];
        if (bm + ar0 + 64 < M)
            av1 = *(const float4*)&A[(size_t)(bm + ar0 + 64) * K + k0 + ac0];
        As[ac0 + 0][ar0] = av0.x;  As[ac0 + 1][ar0] = av0.y;
        As[ac0 + 2][ar0] = av0.z;  As[ac0 + 3][ar0] = av0.w;
        As[ac0 + 0][ar0 + 64] = av1.x;  As[ac0 + 1][ar0 + 64] = av1.y;
        As[ac0 + 2][ar0 + 64] = av1.z;  As[ac0 + 3][ar0 + 64] = av1.w;

        *(float4*)&Bs[br0][bc0] =
            *(const float4*)&B[(size_t)(k0 + br0) * N + bn + bc0];
        *(float4*)&Bs[br0 + 8][bc0] =
            *(const float4*)&B[(size_t)(k0 + br0 + 8) * N + bn + bc0];

        __syncthreads();

#pragma unroll
        for (int kk = 0; kk < BK; kk++) {
            const float4 a0 = *(const float4*)&As[kk][ty * 8];
            const float4 a1 = *(const float4*)&As[kk][ty * 8 + 4];
            unsigned long long am[8] = {pk2(a0.x), pk2(a0.y), pk2(a0.z), pk2(a0.w),
                                        pk2(a1.x), pk2(a1.y), pk2(a1.z), pk2(a1.w)};
            const ulonglong2 bA = *(const ulonglong2*)&Bs[kk][tx * 8];
            const ulonglong2 bB = *(const ulonglong2*)&Bs[kk][tx * 8 + 4];
            unsigned long long bv[4] = {bA.x, bA.y, bB.x, bB.y};
#pragma unroll
            for (int m = 0; m < 8; m++)
#pragma unroll
                for (int n = 0; n < 4; n++)
                    fma2(acc[m][n], am[m], bv[n]);
        }
        __syncthreads();
    }

    // Epilogue
    const int cb = bn + tx * 8;
    const float4 bi0 = *(const float4*)&bias[cb];
    const float4 bi1 = *(const float4*)&bias[cb + 4];
#pragma unroll
    for (int m = 0; m < 8; m++) {
        const int row = bm + ty * 8 + m;
        if (row < M) {
            const float2 c0 = unpk2(acc[m][0]);
            const float2 c1 = unpk2(acc[m][1]);
            const float2 c2 = unpk2(acc[m][2]);
            const float2 c3 = unpk2(acc[m][3]);
            float v0 = c0.x + bi0.x, v1 = c0.y + bi0.y;
            float v2 = c1.x + bi0.z, v3 = c1.y + bi0.w;
            float v4 = c2.x + bi1.x, v5 = c2.y + bi1.y;
            float v6 = c3.x + bi1.z, v7 = c3.y + bi1.w;
            if (EPI == 1) {
                const float4 r0 = *(const float4*)&res[(size_t)row * N + cb];
                const float4 r1 = *(const float4*)&res[(size_t)row * N + cb + 4];
                v0 += r0.x; v1 += r0.y; v2 += r0.z; v3 += r0.w;
                v4 += r1.x; v5 += r1.y; v6 += r1.z; v7 += r1.w;
            } else if (EPI == 2) {
                v0 = gelu_exact(v0); v1 = gelu_exact(v1);
                v2 = gelu_exact(v2); v3 = gelu_exact(v3);
                v4 = gelu_exact(v4); v5 = gelu_exact(v5);
                v6 = gelu_exact(v6); v7 = gelu_exact(v7);
            }
            *(float4*)&C[(size_t)row * N + cb]     = make_float4(v0, v1, v2, v3);
            *(float4*)&C[(size_t)row * N + cb + 4] = make_float4(v4, v5, v6, v7);
        }
    }
}

// ---------------------------------------------------------------------------
// LayerNorm over last dim (C = DM), one block per row
// ---------------------------------------------------------------------------
__global__ void __launch_bounds__(256)
layernorm_kernel(const float* __restrict__ x, const float* __restrict__ w,
                 const float* __restrict__ bta, float* __restrict__ y, int C)
{
    const size_t base = (size_t)blockIdx.x * C;
    float s = 0.f, s2 = 0.f;
    for (int c = threadIdx.x; c < C; c += 256) {
        const float v = x[base + c];
        s += v; s2 += v * v;
    }
#pragma unroll
    for (int o = 16; o; o >>= 1) {
        s  += __shfl_xor_sync(0xffffffffu, s,  o);
        s2 += __shfl_xor_sync(0xffffffffu, s2, o);
    }
    __shared__ float sh[16];
    __shared__ float mv[2];
    const int wid = threadIdx.x >> 5, lane = threadIdx.x & 31;
    if (lane == 0) { sh[wid] = s; sh[8 + wid] = s2; }
    __syncthreads();
    if (threadIdx.x == 0) {
        float ts = 0.f, ts2 = 0.f;
#pragma unroll
        for (int i = 0; i < 8; i++) { ts += sh[i]; ts2 += sh[8 + i]; }
        const float mean = ts / (float)C;
        const float var  = ts2 / (float)C - mean * mean;
        mv[0] = mean;
        mv[1] = rsqrtf(var + 1e-5f);
    }
    __syncthreads();
    const float mean = mv[0], rstd = mv[1];
    for (int c = threadIdx.x; c < C; c += 256)
        y[base + c] = (x[base + c] - mean) * rstd * w[c] + bta[c];
}

// ---------------------------------------------------------------------------
// Cross attention: per (b,h), per 32-query tile.
//   scores[32,257] = Q_tile @ K^T * scale ; softmax over 257 ; ctx = attn @ V
// Dynamic smem: qs[32*288] + ss[32*260] + kv[32*288] = 107,008 B
// ---------------------------------------------------------------------------
#define ATT_TQ 32
#define ATT_KC 32
#define SVP    260
#define ATT_SMEM ((ATT_TQ*DK + ATT_TQ*SVP + ATT_KC*DK) * (int)sizeof(float))

__global__ void __launch_bounds__(256)
attention_kernel(const float* __restrict__ Q, const float* __restrict__ Km,
                 const float* __restrict__ Vm, float* __restrict__ O)
{
    extern __shared__ float sm[];
    float* qs = sm;                        // [ATT_TQ][DK]
    float* ss = qs + ATT_TQ * DK;          // [ATT_TQ][SVP]
    float* kv = ss + ATT_TQ * SVP;         // [ATT_KC][DK]

    const int q0   = blockIdx.x * ATT_TQ;
    const int b    = blockIdx.y / NH;
    const int h    = blockIdx.y % NH;
    const int tid  = threadIdx.x;
    const int lane = tid & 31;
    const int w    = tid >> 5;
    const float scale = 0.05892556509887896f;   // 1/sqrt(288)

    // Load Q tile
    const float* qg = Q + ((size_t)(b * SQ + q0)) * DM + h * DK;
    for (int idx = tid; idx < ATT_TQ * DK; idx += 256) {
        const int r = idx / DK, c = idx - r * DK;
        qs[idx] = qg[(size_t)r * DM + c];
    }
    __syncthreads();

    // Each warp caches its 4 queries in registers (DK = 9 * 32)
    float qr[4][9];
#pragma unroll
    for (int i = 0; i < 4; i++)
#pragma unroll
        for (int t = 0; t < 9; t++)
            qr[i][t] = qs[(w * 4 + i) * DK + lane + t * 32];

    // ---- scores ----
    const float* kg = Km + ((size_t)(b * SV)) * DM + h * DK;
    for (int j0 = 0; j0 < SV; j0 += ATT_KC) {
        const int jn = min(ATT_KC, SV - j0);
        for (int idx = tid; idx < jn * DK; idx += 256) {
            const int r = idx / DK, c = idx - r * DK;
            kv[idx] = kg[(size_t)(j0 + r) * DM + c];
        }
        __syncthreads();
        for (int j = 0; j < jn; j++) {
            float a0 = 0.f, a1 = 0.f, a2 = 0.f, a3 = 0.f;
#pragma unroll
            for (int t = 0; t < 9; t++) {
                const float kvv = kv[j * DK + lane + t * 32];
                a0 += qr[0][t] * kvv;  a1 += qr[1][t] * kvv;
                a2 += qr[2][t] * kvv;  a3 += qr[3][t] * kvv;
            }
#pragma unroll
            for (int o = 16; o; o >>= 1) {
                a0 += __shfl_xor_sync(0xffffffffu, a0, o);
                a1 += __shfl_xor_sync(0xffffffffu, a1, o);
                a2 += __shfl_xor_sync(0xffffffffu, a2, o);
                a3 += __shfl_xor_sync(0xffffffffu, a3, o);
            }
            if (lane == 0) {
                ss[(w * 4 + 0) * SVP + j0 + j] = a0 * scale;
                ss[(w * 4 + 1) * SVP + j0 + j] = a1 * scale;
                ss[(w * 4 + 2) * SVP + j0 + j] = a2 * scale;
                ss[(w * 4 + 3) * SVP + j0 + j] = a3 * scale;
            }
        }
        __syncthreads();
    }

    // ---- softmax (per warp, own 4 rows) ----
#pragma unroll
    for (int i = 0; i < 4; i++) {
        const int q = w * 4 + i;
        float mx = -1e30f;
        for (int j = lane; j < SV; j += 32) mx = fmaxf(mx, ss[q * SVP + j]);
#pragma unroll
        for (int o = 16; o; o >>= 1)
            mx = fmaxf(mx, __shfl_xor_sync(0xffffffffu, mx, o));
        float sum = 0.f;
        for (int j = lane; j < SV; j += 32) {
            const float e = expf(ss[q * SVP + j] - mx);
            ss[q * SVP + j] = e;
            sum += e;
        }
#pragma unroll
        for (int o = 16; o; o >>= 1)
            sum += __shfl_xor_sync(0xffffffffu, sum, o);
        const float inv = 1.f / sum;
        for (int j = lane; j < SV; j += 32) ss[q * SVP + j] *= inv;
    }
    __syncthreads();

    // ---- ctx = attn @ V ----
    const int q  = tid >> 3;          // 0..31
    const int dg = tid & 7;           // 0..7
    const int d0 = dg * 36;
    float4 acc[9];
#pragma unroll
    for (int i = 0; i < 9; i++) acc[i] = make_float4(0.f, 0.f, 0.f, 0.f);

    const float* vg = Vm + ((size_t)(b * SV)) * DM + h * DK;
    for (int j0 = 0; j0 < SV; j0 += ATT_KC) {
        const int jn = min(ATT_KC, SV - j0);
        __syncthreads();   // previous chunk consumers done before overwrite
        for (int idx = tid; idx < jn * DK; idx += 256) {
            const int r = idx / DK, c = idx - r * DK;
            kv[idx] = vg[(size_t)(j0 + r) * DM + c];
        }
        __syncthreads();
        for (int j = 0; j < jn; j++) {
            const float wgt = ss[q * SVP + j0 + j];
#pragma unroll
            for (int i = 0; i < 9; i++) {
                const float4 vv = *(const float4*)&kv[j * DK + d0 + i * 4];
                acc[i].x += wgt * vv.x;  acc[i].y += wgt * vv.y;
                acc[i].z += wgt * vv.z;  acc[i].w += wgt * vv.w;
            }
        }
    }
    float* og = O + ((size_t)(b * SQ + q0 + q)) * DM + h * DK + d0;
#pragma unroll
    for (int i = 0; i < 9; i++) *(float4*)&og[i * 4] = acc[i];
}

// ---------------------------------------------------------------------------
// Orchestration
// ---------------------------------------------------------------------------
extern "C" void kernel_launch(void* const* d_in, const int* in_sizes, int n_in,
                              void* d_out, int out_size)
{
    const float* vision = (const float*)d_in[0];
    const float* text   = (const float*)d_in[1];
    const float* vp_w   = (const float*)d_in[2];
    const float* vp_b   = (const float*)d_in[3];
    const float* ln1_w  = (const float*)d_in[4];
    const float* ln1_b  = (const float*)d_in[5];
    const float* ln2_w  = (const float*)d_in[6];
    const float* ln2_b  = (const float*)d_in[7];
    const float* wq_w   = (const float*)d_in[8];
    const float* wq_b   = (const float*)d_in[9];
    const float* wk_w   = (const float*)d_in[10];
    const float* wk_b   = (const float*)d_in[11];
    const float* wv_w   = (const float*)d_in[12];
    const float* wv_b   = (const float*)d_in[13];
    const float* wo_w   = (const float*)d_in[14];
    const float* wo_b   = (const float*)d_in[15];
    const float* f1_w   = (const float*)d_in[16];
    const float* f1_b   = (const float*)d_in[17];
    const float* f2_w   = (const float*)d_in[18];
    const float* f2_b   = (const float*)d_in[19];
    float* out = (float*)d_out;

    float *pv, *nt, *q, *k, *v, *ctx, *x, *h;
    cudaGetSymbolAddress((void**)&pv,  g_pv);
    cudaGetSymbolAddress((void**)&nt,  g_nt);
    cudaGetSymbolAddress((void**)&q,   g_q);
    cudaGetSymbolAddress((void**)&k,   g_k);
    cudaGetSymbolAddress((void**)&v,   g_v);
    cudaGetSymbolAddress((void**)&ctx, g_ctx);
    cudaGetSymbolAddress((void**)&x,   g_x);
    cudaGetSymbolAddress((void**)&h,   g_h);

    cudaFuncSetAttribute(attention_kernel,
                         cudaFuncAttributeMaxDynamicSharedMemorySize, ATT_SMEM);

    const dim3 blk(256);

    // 1. pv = vision @ vp_w + vp_b            [2056,1024]x[1024,2304]
    sgemm_kernel<0><<<dim3(DM / BN, (ROWS_V + BM - 1) / BM), blk>>>(
        vision, vp_w, vp_b, nullptr, pv, ROWS_V, DM, DV);

    // 2. nt = LN1(text)
    layernorm_kernel<<<ROWS_T, 256>>>(text, ln1_w, ln1_b, nt, DM);

    // 3. q = nt @ wq_w + wq_b                 [16384,2304]x[2304,2304]
    sgemm_kernel<0><<<dim3(DM / BN, ROWS_T / BM), blk>>>(
        nt, wq_w, wq_b, nullptr, q, ROWS_T, DM, DM);

    // 4. k = pv @ wk_w + wk_b
    sgemm_kernel<0><<<dim3(DM / BN, (ROWS_V + BM - 1) / BM), blk>>>(
        pv, wk_w, wk_b, nullptr, k, ROWS_V, DM, DM);

    // 5. v = pv @ wv_w + wv_b
    sgemm_kernel<0><<<dim3(DM / BN, (ROWS_V + BM - 1) / BM), blk>>>(
        pv, wv_w, wv_b, nullptr, v, ROWS_V, DM, DM);

    // 6. ctx = softmax(q k^T / sqrt(dk)) v
    attention_kernel<<<dim3(SQ / ATT_TQ, BATCH * NH), 256, ATT_SMEM>>>(
        q, k, v, ctx);

    // 7. x = text + ctx @ wo_w + wo_b
    sgemm_kernel<1><<<dim3(DM / BN, ROWS_T / BM), blk>>>(
        ctx, wo_w, wo_b, text, x, ROWS_T, DM, DM);

    // 8. nt = LN2(x)
    layernorm_kernel<<<ROWS_T, 256>>>(x, ln2_w, ln2_b, nt, DM);

    // 9. h = gelu(nt @ f1_w + f1_b)           [16384,2304]x[2304,9216]
    sgemm_kernel<2><<<dim3(DF / BN, ROWS_T / BM), blk>>>(
        nt, f1_w, f1_b, nullptr, h, ROWS_T, DF, DM);

    // 10. out = x + h @ f2_w + f2_b           [16384,9216]x[9216,2304]
    sgemm_kernel<1><<<dim3(DM / BN, ROWS_T / BM), blk>>>(
        h, f2_w, f2_b, x, out, ROWS_T, DM, DF);
}

// round 3
// speedup vs baseline: 3.0208x; 3.0208x over previous
#include <cuda_runtime.h>
#include <cuda_bf16.h>
#include <math.h>
#include <cstdint>

// ---------------------------------------------------------------------------
// Problem constants
// ---------------------------------------------------------------------------
#define BATCH 8
#define SV    257
#define SQ    2048
#define DV    1024
#define DM    2304
#define NH    8
#define DK    288
#define DF    9216
#define ROWS_T (BATCH*SQ)  // 16384
#define ROWS_V (BATCH*SV)  // 2056

// ---------------------------------------------------------------------------
// Scratch (device globals; no runtime allocation allowed)
// ---------------------------------------------------------------------------
__device__ float g_pv [(size_t)ROWS_V * DM];
__device__ float g_nt [(size_t)ROWS_T * DM];
__device__ float g_q  [(size_t)ROWS_T * DM];
__device__ float g_k  [(size_t)ROWS_V * DM];
__device__ float g_v  [(size_t)ROWS_V * DM];
__device__ float g_ctx[(size_t)ROWS_T * DM];
__device__ float g_x  [(size_t)ROWS_T * DM];
__device__ float g_h  [(size_t)ROWS_T * DF];

// ---------------------------------------------------------------------------
// helpers
// ---------------------------------------------------------------------------
__device__ __forceinline__ uint32_t smem_u32(const void* p) {
    uint32_t a;
    asm("{ .reg .u64 t; cvta.to.shared.u64 t, %1; cvt.u32.u64 %0, t; }"
        : "=r"(a) : "l"(p));
    return a;
}
__device__ __forceinline__ void cp16(uint32_t dst, const void* src, uint32_t n) {
    asm volatile("cp.async.cg.shared.global [%0], [%1], 16, %2;"
                 :: "r"(dst), "l"(src), "r"(n) : "memory");
}
__device__ __forceinline__ uint32_t f2tf(float x) {
    uint32_t r;
    asm("cvt.rna.tf32.f32 %0, %1;" : "=r"(r) : "f"(x));
    return r;
}
__device__ __forceinline__ void mma_tf32(float* c, const uint32_t* a,
                                         const uint32_t* b) {
    asm volatile(
        "mma.sync.aligned.m16n8k8.row.col.f32.tf32.tf32.f32 "
        "{%0,%1,%2,%3}, {%4,%5,%6,%7}, {%8,%9}, {%0,%1,%2,%3};"
        : "+f"(c[0]), "+f"(c[1]), "+f"(c[2]), "+f"(c[3])
        : "r"(a[0]), "r"(a[1]), "r"(a[2]), "r"(a[3]), "r"(b[0]), "r"(b[1]));
}
__device__ __forceinline__ float gelu_exact(float x) {
    return 0.5f * x * (1.0f + erff(x * 0.70710678118654752f));
}

// ---------------------------------------------------------------------------
// tf32 HMMA GEMM: C[M,N] = A[M,K] @ B[K,N] + bias (+ epilogue)
//   EPI 0: +bias   EPI 1: +bias+res   EPI 2: gelu(+bias)
// CTA tile 128x256, KC=32, 3-stage cp.async, 8 warps x (64x64) warp tiles.
// Requires: K % 32 == 0, N % 256 == 0. M tail handled.
// ---------------------------------------------------------------------------
#define TM 128
#define TN 256
#define KC 32
#define NSTG 3
#define A_BYTES 16384                 // 128 x 32 x 4
#define STG_BYTES 49152               // A 16KB + B 32KB
#define GEMM_SMEM (NSTG * STG_BYTES)  // 147456

// A smem: row-major [128][32] floats, col swizz: c = (k + 4*(row&7)) & 31
// B smem: row-major [32][256] floats, col swizz: c = (n&~31) | ((n + 8*(k&3)) & 31)

__device__ __forceinline__ void load_stage(
    const float* __restrict__ A, const float* __restrict__ Bw,
    int M, int N, int K, uint32_t stg, int bm, int n0, int kc, int tid)
{
#pragma unroll
    for (int i = 0; i < 4; i++) {            // A: 1024 cp16 / 256 thr
        const int ai = tid + i * 256;
        const int row = ai >> 3, c4 = ai & 7;
        const uint32_t col = (uint32_t)((c4 * 4 + 4 * (row & 7)) & 31);
        const uint32_t dst = stg + row * 128 + col * 4;
        const int gr = bm + row;
        const int ok = gr < M;
        const float* src = A + (size_t)(ok ? gr : 0) * K + kc + c4 * 4;
        cp16(dst, src, ok ? 16u : 0u);
    }
#pragma unroll
    for (int i = 0; i < 8; i++) {            // B: 2048 cp16 / 256 thr
        const int bi = tid + i * 256;
        const int k = bi >> 6, c4 = bi & 63;
        const int n = c4 * 4;
        const uint32_t col = (uint32_t)((n & ~31) | ((n + 8 * (k & 3)) & 31));
        const uint32_t dst = stg + A_BYTES + k * 1024 + col * 4;
        const float* src = Bw + (size_t)(kc + k) * N + n0 + n;
        cp16(dst, src, 16u);
    }
}

template <int EPI>
__global__ void __launch_bounds__(256, 1)
tgemm(const float* __restrict__ A, const float* __restrict__ Bw,
      const float* __restrict__ bias, const float* __restrict__ res,
      float* __restrict__ C, int M, int N, int K)
{
    extern __shared__ char smem[];
    const uint32_t sb = smem_u32(smem);
    const int tid  = threadIdx.x;
    const int lane = tid & 31;
    const int wid  = tid >> 5;
    const int wm   = (wid >> 2) * 64;     // warp row offset (0, 64)
    const int wn   = (wid & 3) * 64;      // warp col offset (0..192)
    const int bm   = blockIdx.y * TM;
    const int n0   = blockIdx.x * TN;
    const int nch  = K / KC;

    float c[4][8][4];
#pragma unroll
    for (int mt = 0; mt < 4; mt++)
#pragma unroll
        for (int nt = 0; nt < 8; nt++)
#pragma unroll
            for (int r = 0; r < 4; r++) c[mt][nt][r] = 0.f;

    // prologue: stages 0,1
    load_stage(A, Bw, M, N, K, sb, bm, n0, 0, tid);
    asm volatile("cp.async.commit_group;" ::: "memory");
    load_stage(A, Bw, M, N, K, sb + STG_BYTES, bm, n0, KC, tid);
    asm volatile("cp.async.commit_group;" ::: "memory");

    const int l4 = lane >> 2;      // 0..7
    const int lk = lane & 3;       // 0..3

    for (int chunk = 0; chunk < nch; ++chunk) {
        asm volatile("cp.async.wait_group 1;" ::: "memory");
        __syncthreads();

        const char* stage = smem + (chunk % NSTG) * STG_BYTES;
        const float* As = (const float*)stage;
        const float* Bs = (const float*)(stage + A_BYTES);

#pragma unroll
        for (int ks = 0; ks < 4; ks++) {
            const int k0 = ks * 8 + lk;
            const int k1 = k0 + 4;
            uint32_t a[4][4], b[8][2];
#pragma unroll
            for (int mt = 0; mt < 4; mt++) {
                const int r0 = wm + mt * 16 + l4;
                const int r1 = r0 + 8;
                a[mt][0] = f2tf(As[r0 * 32 + ((k0 + 4 * (r0 & 7)) & 31)]);
                a[mt][1] = f2tf(As[r1 * 32 + ((k0 + 4 * (r1 & 7)) & 31)]);
                a[mt][2] = f2tf(As[r0 * 32 + ((k1 + 4 * (r0 & 7)) & 31)]);
                a[mt][3] = f2tf(As[r1 * 32 + ((k1 + 4 * (r1 & 7)) & 31)]);
            }
#pragma unroll
            for (int nt = 0; nt < 8; nt++) {
                const int n = wn + nt * 8 + l4;
                const int sw = (n & ~31);
                b[nt][0] = f2tf(Bs[k0 * 256 + (sw | ((n + 8 * (k0 & 3)) & 31))]);
                b[nt][1] = f2tf(Bs[k1 * 256 + (sw | ((n + 8 * (k1 & 3)) & 31))]);
            }
#pragma unroll
            for (int mt = 0; mt < 4; mt++)
#pragma unroll
                for (int nt = 0; nt < 8; nt++)
                    mma_tf32(c[mt][nt], a[mt], b[nt]);
        }

        const int nx = chunk + 2;
        if (nx < nch)
            load_stage(A, Bw, M, N, K, sb + (nx % NSTG) * STG_BYTES,
                       bm, n0, nx * KC, tid);
        asm volatile("cp.async.commit_group;" ::: "memory");
    }

    // -------- epilogue --------
#pragma unroll
    for (int mt = 0; mt < 4; mt++) {
        const int rb = bm + wm + mt * 16 + l4;
#pragma unroll
        for (int hh = 0; hh < 2; hh++) {
            const int row = rb + hh * 8;
            if (row < M) {
#pragma unroll
                for (int nt = 0; nt < 8; nt++) {
                    const int col = n0 + wn + nt * 8 + lk * 2;
                    float v0 = c[mt][nt][hh * 2 + 0] + bias[col];
                    float v1 = c[mt][nt][hh * 2 + 1] + bias[col + 1];
                    if (EPI == 1) {
                        const float2 r2 = *(const float2*)&res[(size_t)row * N + col];
                        v0 += r2.x; v1 += r2.y;
                    } else if (EPI == 2) {
                        v0 = gelu_exact(v0); v1 = gelu_exact(v1);
                    }
                    *(float2*)&C[(size_t)row * N + col] = make_float2(v0, v1);
                }
            }
        }
    }
}

// ---------------------------------------------------------------------------
// LayerNorm over last dim (C = DM), one block per row
// ---------------------------------------------------------------------------
__global__ void __launch_bounds__(256)
layernorm_kernel(const float* __restrict__ x, const float* __restrict__ w,
                 const float* __restrict__ bta, float* __restrict__ y, int C)
{
    const size_t base = (size_t)blockIdx.x * C;
    float s = 0.f, s2 = 0.f;
    for (int c = threadIdx.x; c < C; c += 256) {
        const float v = x[base + c];
        s += v; s2 += v * v;
    }
#pragma unroll
    for (int o = 16; o; o >>= 1) {
        s  += __shfl_xor_sync(0xffffffffu, s,  o);
        s2 += __shfl_xor_sync(0xffffffffu, s2, o);
    }
    __shared__ float sh[16];
    __shared__ float mv[2];
    const int wid = threadIdx.x >> 5, lane = threadIdx.x & 31;
    if (lane == 0) { sh[wid] = s; sh[8 + wid] = s2; }
    __syncthreads();
    if (threadIdx.x == 0) {
        float ts = 0.f, ts2 = 0.f;
#pragma unroll
        for (int i = 0; i < 8; i++) { ts += sh[i]; ts2 += sh[8 + i]; }
        const float mean = ts / (float)C;
        const float var  = ts2 / (float)C - mean * mean;
        mv[0] = mean;
        mv[1] = rsqrtf(var + 1e-5f);
    }
    __syncthreads();
    const float mean = mv[0], rstd = mv[1];
    for (int c = threadIdx.x; c < C; c += 256)
        y[base + c] = (x[base + c] - mean) * rstd * w[c] + bta[c];
}

// ---------------------------------------------------------------------------
// Cross attention (fp32) — unchanged from R1 (passing)
// ---------------------------------------------------------------------------
#define ATT_TQ 32
#define ATT_KC 32
#define SVP    260
#define ATT_SMEM ((ATT_TQ*DK + ATT_TQ*SVP + ATT_KC*DK) * (int)sizeof(float))

__global__ void __launch_bounds__(256)
attention_kernel(const float* __restrict__ Q, const float* __restrict__ Km,
                 const float* __restrict__ Vm, float* __restrict__ O)
{
    extern __shared__ float sm[];
    float* qs = sm;
    float* ss = qs + ATT_TQ * DK;
    float* kv = ss + ATT_TQ * SVP;

    const int q0   = blockIdx.x * ATT_TQ;
    const int b    = blockIdx.y / NH;
    const int h    = blockIdx.y % NH;
    const int tid  = threadIdx.x;
    const int lane = tid & 31;
    const int w    = tid >> 5;
    const float scale = 0.05892556509887896f;   // 1/sqrt(288)

    const float* qg = Q + ((size_t)(b * SQ + q0)) * DM + h * DK;
    for (int idx = tid; idx < ATT_TQ * DK; idx += 256) {
        const int r = idx / DK, c = idx - r * DK;
        qs[idx] = qg[(size_t)r * DM + c];
    }
    __syncthreads();

    float qr[4][9];
#pragma unroll
    for (int i = 0; i < 4; i++)
#pragma unroll
        for (int t = 0; t < 9; t++)
            qr[i][t] = qs[(w * 4 + i) * DK + lane + t * 32];

    const float* kg = Km + ((size_t)(b * SV)) * DM + h * DK;
    for (int j0 = 0; j0 < SV; j0 += ATT_KC) {
        const int jn = min(ATT_KC, SV - j0);
        for (int idx = tid; idx < jn * DK; idx += 256) {
            const int r = idx / DK, c = idx - r * DK;
            kv[idx] = kg[(size_t)(j0 + r) * DM + c];
        }
        __syncthreads();
        for (int j = 0; j < jn; j++) {
            float a0 = 0.f, a1 = 0.f, a2 = 0.f, a3 = 0.f;
#pragma unroll
            for (int t = 0; t < 9; t++) {
                const float kvv = kv[j * DK + lane + t * 32];
                a0 += qr[0][t] * kvv;  a1 += qr[1][t] * kvv;
                a2 += qr[2][t] * kvv;  a3 += qr[3][t] * kvv;
            }
#pragma unroll
            for (int o = 16; o; o >>= 1) {
                a0 += __shfl_xor_sync(0xffffffffu, a0, o);
                a1 += __shfl_xor_sync(0xffffffffu, a1, o);
                a2 += __shfl_xor_sync(0xffffffffu, a2, o);
                a3 += __shfl_xor_sync(0xffffffffu, a3, o);
            }
            if (lane == 0) {
                ss[(w * 4 + 0) * SVP + j0 + j] = a0 * scale;
                ss[(w * 4 + 1) * SVP + j0 + j] = a1 * scale;
                ss[(w * 4 + 2) * SVP + j0 + j] = a2 * scale;
                ss[(w * 4 + 3) * SVP + j0 + j] = a3 * scale;
            }
        }
        __syncthreads();
    }

#pragma unroll
    for (int i = 0; i < 4; i++) {
        const int q = w * 4 + i;
        float mx = -1e30f;
        for (int j = lane; j < SV; j += 32) mx = fmaxf(mx, ss[q * SVP + j]);
#pragma unroll
        for (int o = 16; o; o >>= 1)
            mx = fmaxf(mx, __shfl_xor_sync(0xffffffffu, mx, o));
        float sum = 0.f;
        for (int j = lane; j < SV; j += 32) {
            const float e = expf(ss[q * SVP + j] - mx);
            ss[q * SVP + j] = e;
            sum += e;
        }
#pragma unroll
        for (int o = 16; o; o >>= 1)
            sum += __shfl_xor_sync(0xffffffffu, sum, o);
        const float inv = 1.f / sum;
        for (int j = lane; j < SV; j += 32) ss[q * SVP + j] *= inv;
    }
    __syncthreads();

    const int q  = tid >> 3;
    const int dg = tid & 7;
    const int d0 = dg * 36;
    float4 acc[9];
#pragma unroll
    for (int i = 0; i < 9; i++) acc[i] = make_float4(0.f, 0.f, 0.f, 0.f);

    const float* vg = Vm + ((size_t)(b * SV)) * DM + h * DK;
    for (int j0 = 0; j0 < SV; j0 += ATT_KC) {
        const int jn = min(ATT_KC, SV - j0);
        __syncthreads();
        for (int idx = tid; idx < jn * DK; idx += 256) {
            const int r = idx / DK, c = idx - r * DK;
            kv[idx] = vg[(size_t)(j0 + r) * DM + c];
        }
        __syncthreads();
        for (int j = 0; j < jn; j++) {
            const float wgt = ss[q * SVP + j0 + j];
#pragma unroll
            for (int i = 0; i < 9; i++) {
                const float4 vv = *(const float4*)&kv[j * DK + d0 + i * 4];
                acc[i].x += wgt * vv.x;  acc[i].y += wgt * vv.y;
                acc[i].z += wgt * vv.z;  acc[i].w += wgt * vv.w;
            }
        }
    }
    float* og = O + ((size_t)(b * SQ + q0 + q)) * DM + h * DK + d0;
#pragma unroll
    for (int i = 0; i < 9; i++) *(float4*)&og[i * 4] = acc[i];
}

// ---------------------------------------------------------------------------
// Orchestration
// ---------------------------------------------------------------------------
extern "C" void kernel_launch(void* const* d_in, const int* in_sizes, int n_in,
                              void* d_out, int out_size)
{
    const float* vision = (const float*)d_in[0];
    const float* text   = (const float*)d_in[1];
    const float* vp_w   = (const float*)d_in[2];
    const float* vp_b   = (const float*)d_in[3];
    const float* ln1_w  = (const float*)d_in[4];
    const float* ln1_b  = (const float*)d_in[5];
    const float* ln2_w  = (const float*)d_in[6];
    const float* ln2_b  = (const float*)d_in[7];
    const float* wq_w   = (const float*)d_in[8];
    const float* wq_b   = (const float*)d_in[9];
    const float* wk_w   = (const float*)d_in[10];
    const float* wk_b   = (const float*)d_in[11];
    const float* wv_w   = (const float*)d_in[12];
    const float* wv_b   = (const float*)d_in[13];
    const float* wo_w   = (const float*)d_in[14];
    const float* wo_b   = (const float*)d_in[15];
    const float* f1_w   = (const float*)d_in[16];
    const float* f1_b   = (const float*)d_in[17];
    const float* f2_w   = (const float*)d_in[18];
    const float* f2_b   = (const float*)d_in[19];
    float* out = (float*)d_out;

    float *pv, *nt, *q, *k, *v, *ctx, *x, *h;
    cudaGetSymbolAddress((void**)&pv,  g_pv);
    cudaGetSymbolAddress((void**)&nt,  g_nt);
    cudaGetSymbolAddress((void**)&q,   g_q);
    cudaGetSymbolAddress((void**)&k,   g_k);
    cudaGetSymbolAddress((void**)&v,   g_v);
    cudaGetSymbolAddress((void**)&ctx, g_ctx);
    cudaGetSymbolAddress((void**)&x,   g_x);
    cudaGetSymbolAddress((void**)&h,   g_h);

    cudaFuncSetAttribute(tgemm<0>, cudaFuncAttributeMaxDynamicSharedMemorySize, GEMM_SMEM);
    cudaFuncSetAttribute(tgemm<1>, cudaFuncAttributeMaxDynamicSharedMemorySize, GEMM_SMEM);
    cudaFuncSetAttribute(tgemm<2>, cudaFuncAttributeMaxDynamicSharedMemorySize, GEMM_SMEM);
    cudaFuncSetAttribute(attention_kernel,
                         cudaFuncAttributeMaxDynamicSharedMemorySize, ATT_SMEM);

    const dim3 blk(256);
    const int mtV = (ROWS_V + TM - 1) / TM;   // 17
    const int mtT = ROWS_T / TM;              // 128

    // 1. pv = vision @ vp_w + vp_b            [2056,1024]x[1024,2304]
    tgemm<0><<<dim3(DM / TN, mtV), blk, GEMM_SMEM>>>(
        vision, vp_w, vp_b, nullptr, pv, ROWS_V, DM, DV);

    // 2. nt = LN1(text)
    layernorm_kernel<<<ROWS_T, 256>>>(text, ln1_w, ln1_b, nt, DM);

    // 3. q = nt @ wq_w + wq_b                 [16384,2304]x[2304,2304]
    tgemm<0><<<dim3(DM / TN, mtT), blk, GEMM_SMEM>>>(
        nt, wq_w, wq_b, nullptr, q, ROWS_T, DM, DM);

    // 4. k = pv @ wk_w + wk_b
    tgemm<0><<<dim3(DM / TN, mtV), blk, GEMM_SMEM>>>(
        pv, wk_w, wk_b, nullptr, k, ROWS_V, DM, DM);

    // 5. v = pv @ wv_w + wv_b
    tgemm<0><<<dim3(DM / TN, mtV), blk, GEMM_SMEM>>>(
        pv, wv_w, wv_b, nullptr, v, ROWS_V, DM, DM);

    // 6. ctx = softmax(q k^T / sqrt(dk)) v
    attention_kernel<<<dim3(SQ / ATT_TQ, BATCH * NH), 256, ATT_SMEM>>>(
        q, k, v, ctx);

    // 7. x = text + ctx @ wo_w + wo_b
    tgemm<1><<<dim3(DM / TN, mtT), blk, GEMM_SMEM>>>(
        ctx, wo_w, wo_b, text, x, ROWS_T, DM, DM);

    // 8. nt = LN2(x)
    layernorm_kernel<<<ROWS_T, 256>>>(x, ln2_w, ln2_b, nt, DM);

    // 9. h = gelu(nt @ f1_w + f1_b)           [16384,2304]x[2304,9216]
    tgemm<2><<<dim3(DF / TN, mtT), blk, GEMM_SMEM>>>(
        nt, f1_w, f1_b, nullptr, h, ROWS_T, DF, DM);

    // 10. out = x + h @ f2_w + f2_b           [16384,9216]x[9216,2304]
    tgemm<1><<<dim3(DM / TN, mtT), blk, GEMM_SMEM>>>(
        h, f2_w, f2_b, x, out, ROWS_T, DM, DF);
}